// round 16
// baseline (speedup 1.0000x reference)
#include <cuda_runtime.h>
#include <cuda_bf16.h>
#include <cstdint>

// Problem constants (fixed by the reference)
#define NODES 100000
#define EDGES 1600000
#define IN_C  128
#define HID_C 128
#define OUT_C 64

#define SCAN_B 1024
#define SCAN_NB ((NODES + SCAN_B - 1) / SCAN_B)   // 98

// -------- scratch (no allocation allowed -> __device__ globals) --------
__device__ int   g_odeg[NODES];          // out-degree (src histogram, built in fill)
__device__ int   g_cnt[NODES];           // in-degree (dst histogram)
__device__ int   g_off[NODES + 1];       // CSR offsets (by dst)
__device__ int   g_cur[NODES];           // fill cursors
__device__ int   g_csr[EDGES];           // src ids grouped by dst
__device__ int   g_bsum[SCAN_NB + 1];    // scan block sums (raw inclusive totals)
__device__ float g_h1[NODES * HID_C];    // scaled projection, layer 1
__device__ float g_out1[NODES * HID_C];  // relu input (aggregated + b1)
__device__ float g_h2[NODES * OUT_C];    // scaled projection, layer 2
// pre-split, k-pair-packed weights: [K/2][N] of uint32 {lo=bf16(W[2k]), hi=bf16(W[2k+1])}
__device__ uint32_t g_w1h[(IN_C / 2) * HID_C];
__device__ uint32_t g_w1l[(IN_C / 2) * HID_C];
__device__ uint32_t g_w2h[(HID_C / 2) * OUT_C];
__device__ uint32_t g_w2l[(HID_C / 2) * OUT_C];

// -------- in-degree histogram only (dst); odeg is built in fill --------
__global__ void hist_kernel(const int* __restrict__ dst) {
    int i = blockIdx.x * blockDim.x + threadIdx.x;
    if (i < EDGES) atomicAdd(&g_cnt[dst[i]], 1);
}

// -------- weight split: W -> bf16 hi + bf16 residual, k-pair packed --------
__device__ __forceinline__ uint32_t pack_bf16_pair(float x0, float x1) {
    uint32_t r;
    asm("cvt.rn.bf16x2.f32 %0, %1, %2;" : "=r"(r) : "f"(x1), "f"(x0));
    return r;
}

__global__ void wsplit_kernel(const float* __restrict__ W1,
                              const float* __restrict__ W2) {
    int i = blockIdx.x * blockDim.x + threadIdx.x;
    if (i < (IN_C / 2) * HID_C) {
        int kp = i / HID_C, n = i % HID_C;
        float w0 = W1[(2 * kp) * HID_C + n];
        float w1 = W1[(2 * kp + 1) * HID_C + n];
        uint32_t h = pack_bf16_pair(w0, w1);
        float h0 = __uint_as_float(h << 16);
        float h1 = __uint_as_float(h & 0xFFFF0000u);
        g_w1h[i] = h;
        g_w1l[i] = pack_bf16_pair(w0 - h0, w1 - h1);
    }
    if (i < (HID_C / 2) * OUT_C) {
        int kp = i / OUT_C, n = i % OUT_C;
        float w0 = W2[(2 * kp) * OUT_C + n];
        float w1 = W2[(2 * kp + 1) * OUT_C + n];
        uint32_t h = pack_bf16_pair(w0, w1);
        float h0 = __uint_as_float(h << 16);
        float h1 = __uint_as_float(h & 0xFFFF0000u);
        g_w2h[i] = h;
        g_w2l[i] = pack_bf16_pair(w0 - h0, w1 - h1);
    }
}

// -------- 2-kernel exclusive scan of g_cnt -> g_off --------
__global__ __launch_bounds__(SCAN_B) void scan1_kernel() {
    int gi = blockIdx.x * SCAN_B + threadIdx.x;
    int v = (gi < NODES) ? g_cnt[gi] : 0;
    int lane = threadIdx.x & 31, w = threadIdx.x >> 5;
    int x = v;
#pragma unroll
    for (int o = 1; o < 32; o <<= 1) {
        int y = __shfl_up_sync(0xffffffffu, x, o);
        if (lane >= o) x += y;
    }
    __shared__ int wsum[32];
    if (lane == 31) wsum[w] = x;
    __syncthreads();
    if (w == 0) {
        int s = wsum[lane];
#pragma unroll
        for (int o = 1; o < 32; o <<= 1) {
            int y = __shfl_up_sync(0xffffffffu, s, o);
            if (lane >= o) s += y;
        }
        wsum[lane] = s;
    }
    __syncthreads();
    int incl = x + (w > 0 ? wsum[w - 1] : 0);
    if (gi < NODES) g_off[gi] = incl - v;           // block-local exclusive
    if (threadIdx.x == SCAN_B - 1) g_bsum[blockIdx.x] = incl;   // raw block totals
}

// scan3: each block reduces g_bsum[0..bid) itself (<=98 ints) -- scan2 deleted
__global__ __launch_bounds__(SCAN_B) void scan3_kernel() {
    __shared__ int warp_part[32];
    int tid = threadIdx.x;
    int bid = blockIdx.x;
    int lane = tid & 31, w = tid >> 5;

    int contrib = (tid < bid) ? g_bsum[tid] : 0;   // bid < SCAN_NB <= 98 < 1024
#pragma unroll
    for (int o = 16; o > 0; o >>= 1) contrib += __shfl_down_sync(0xffffffffu, contrib, o);
    if (lane == 0) warp_part[w] = contrib;
    __syncthreads();
    if (w == 0) {
        int v = warp_part[lane];
#pragma unroll
        for (int o = 16; o > 0; o >>= 1) v += __shfl_down_sync(0xffffffffu, v, o);
        if (lane == 0) warp_part[0] = v;
    }
    __syncthreads();
    int base = warp_part[0];

    int gi = bid * SCAN_B + tid;
    if (gi < NODES) {
        int o = g_off[gi] + base;
        g_off[gi] = o;
        g_cur[gi] = o;
    }
    if (gi == 0) g_off[NODES] = EDGES;
}

// -------- CSR fill: bucket src ids by dst; also builds out-degree --------
__global__ void fill_kernel(const int* __restrict__ src,
                            const int* __restrict__ dst) {
    int i = blockIdx.x * blockDim.x + threadIdx.x;
    if (i < EDGES) {
        int s = src[i];
        atomicAdd(&g_odeg[s], 1);
        int p = atomicAdd(&g_cur[dst[i]], 1);
        g_csr[p] = s;
    }
}

// ===================== split-BF16 tensor-core GEMM =====================
// C[M,NOUT] = op(A[M,128]) @ B[128,NOUT], scaled by 1/max(odeg[row],1).
// a = ah + al (bf16 hi + bf16 residual); B pre-split the same way.
// D += ah*bh + ah*bl + al*bh  ->  ~eps_bf16^2 accuracy.
// Tile: BM=128, BN=64, KC=32. 256 threads = 8 warps; warp = 16 rows x 64 cols.

__device__ __forceinline__ void mma_bf16(float c[4],
                                         uint32_t a0, uint32_t a1, uint32_t a2, uint32_t a3,
                                         uint32_t b0, uint32_t b1) {
    asm volatile(
        "mma.sync.aligned.m16n8k16.row.col.f32.bf16.bf16.f32 "
        "{%0,%1,%2,%3}, {%4,%5,%6,%7}, {%8,%9}, {%0,%1,%2,%3};\n"
        : "+f"(c[0]), "+f"(c[1]), "+f"(c[2]), "+f"(c[3])
        : "r"(a0), "r"(a1), "r"(a2), "r"(a3), "r"(b0), "r"(b1));
}

__device__ __forceinline__ void split_pair(float x0, float x1,
                                           uint32_t& h, uint32_t& l) {
    h = pack_bf16_pair(x0, x1);
    float h0 = __uint_as_float(h << 16);
    float h1 = __uint_as_float(h & 0xFFFF0000u);
    l = pack_bf16_pair(x0 - h0, x1 - h1);
}

template <int NOUT, bool SECOND>
__global__ __launch_bounds__(256) void gemm_tc_kernel(const float* __restrict__ Ain,
                                                      const uint32_t* __restrict__ Bh,
                                                      const uint32_t* __restrict__ Bl,
                                                      int M) {
    constexpr int BM = 128, BN = 64, KC = 32;
    constexpr int APITCH = 40;
    constexpr int BPITCH = 72;

    const float* A = SECOND ? g_out1 : Ain;
    float*       C = SECOND ? g_h2   : g_h1;

    __shared__ float    As [BM * APITCH];
    __shared__ uint32_t Bsh[(KC / 2) * BPITCH];
    __shared__ uint32_t Bsl[(KC / 2) * BPITCH];

    const int tid  = threadIdx.x;
    const int lane = tid & 31;
    const int wid  = tid >> 5;
    const int rowBase = blockIdx.y * BM;
    const int colBase = blockIdx.x * BN;
    const int wrow = wid * 16;

    const int g = lane >> 2;
    const int t = lane & 3;

    float c[8][4];
#pragma unroll
    for (int nt = 0; nt < 8; nt++)
#pragma unroll
        for (int j = 0; j < 4; j++) c[nt][j] = 0.0f;

    for (int k0 = 0; k0 < 128; k0 += KC) {
#pragma unroll
        for (int i = tid; i < BM * KC / 4; i += 256) {
            int r = i >> 3;
            int q = i & 7;
            int grow = rowBase + r;
            float4 a = make_float4(0.f, 0.f, 0.f, 0.f);
            if (grow < M)
                a = *reinterpret_cast<const float4*>(A + (size_t)grow * 128 + k0 + q * 4);
            if (SECOND) {
                a.x = fmaxf(a.x, 0.f); a.y = fmaxf(a.y, 0.f);
                a.z = fmaxf(a.z, 0.f); a.w = fmaxf(a.w, 0.f);
            }
            *reinterpret_cast<float4*>(&As[r * APITCH + q * 4]) = a;
        }
        {
            int kp = tid >> 4;
            int nq = tid & 15;
            size_t goff = (size_t)(k0 / 2 + kp) * NOUT + colBase + nq * 4;
            *reinterpret_cast<uint4*>(&Bsh[kp * BPITCH + nq * 4]) =
                *reinterpret_cast<const uint4*>(Bh + goff);
            *reinterpret_cast<uint4*>(&Bsl[kp * BPITCH + nq * 4]) =
                *reinterpret_cast<const uint4*>(Bl + goff);
        }
        __syncthreads();

#pragma unroll
        for (int kk = 0; kk < KC; kk += 16) {
            float2 p0 = *reinterpret_cast<const float2*>(&As[(wrow + g)     * APITCH + kk + 2 * t]);
            float2 p1 = *reinterpret_cast<const float2*>(&As[(wrow + g + 8) * APITCH + kk + 2 * t]);
            float2 p2 = *reinterpret_cast<const float2*>(&As[(wrow + g)     * APITCH + kk + 2 * t + 8]);
            float2 p3 = *reinterpret_cast<const float2*>(&As[(wrow + g + 8) * APITCH + kk + 2 * t + 8]);
            uint32_t ah0, al0, ah1, al1, ah2, al2, ah3, al3;
            split_pair(p0.x, p0.y, ah0, al0);
            split_pair(p1.x, p1.y, ah1, al1);
            split_pair(p2.x, p2.y, ah2, al2);
            split_pair(p3.x, p3.y, ah3, al3);

            const int kb = kk / 2;
#pragma unroll
            for (int nt = 0; nt < 8; nt++) {
                uint32_t bh0 = Bsh[(kb + t)     * BPITCH + nt * 8 + g];
                uint32_t bh1 = Bsh[(kb + t + 4) * BPITCH + nt * 8 + g];
                uint32_t bl0 = Bsl[(kb + t)     * BPITCH + nt * 8 + g];
                uint32_t bl1 = Bsl[(kb + t + 4) * BPITCH + nt * 8 + g];
                mma_bf16(c[nt], ah0, ah1, ah2, ah3, bh0, bh1);
                mma_bf16(c[nt], ah0, ah1, ah2, ah3, bl0, bl1);
                mma_bf16(c[nt], al0, al1, al2, al3, bh0, bh1);
            }
        }
        __syncthreads();
    }

    // ---- epilogue: scale by 1/max(odeg,1) computed inline, store ----
    int r0 = rowBase + wrow + g;
    int r1 = r0 + 8;
    float s0 = (r0 < M) ? (1.0f / fmaxf((float)g_odeg[r0], 1.0f)) : 0.f;
    float s1 = (r1 < M) ? (1.0f / fmaxf((float)g_odeg[r1], 1.0f)) : 0.f;
#pragma unroll
    for (int nt = 0; nt < 8; nt++) {
        int col = colBase + nt * 8 + 2 * t;
        if (r0 < M) {
            float2 o = make_float2(c[nt][0] * s0, c[nt][1] * s0);
            *reinterpret_cast<float2*>(C + (size_t)r0 * NOUT + col) = o;
        }
        if (r1 < M) {
            float2 o = make_float2(c[nt][2] * s1, c[nt][3] * s1);
            *reinterpret_cast<float2*>(C + (size_t)r1 * NOUT + col) = o;
        }
    }
}

// -------- layer-1 aggregate: warp per dst node, 32 x float4 = 128 ch ------
__global__ __launch_bounds__(256) void agg128_kernel(const float* __restrict__ b1) {
    int gw = (blockIdx.x * blockDim.x + threadIdx.x) >> 5;
    int lane = threadIdx.x & 31;
    if (gw >= NODES) return;
    int beg = g_off[gw], end = g_off[gw + 1];
    const float4* __restrict__ H = reinterpret_cast<const float4*>(g_h1);

    float4 a0 = make_float4(0.f, 0.f, 0.f, 0.f);
    float4 a1 = make_float4(0.f, 0.f, 0.f, 0.f);
    float4 a2 = make_float4(0.f, 0.f, 0.f, 0.f);
    float4 a3 = make_float4(0.f, 0.f, 0.f, 0.f);
    int e = beg;
    for (; e + 3 < end; e += 4) {
        int s0 = g_csr[e];
        int s1 = g_csr[e + 1];
        int s2 = g_csr[e + 2];
        int s3 = g_csr[e + 3];
        float4 v0 = H[s0 * 32 + lane];
        float4 v1 = H[s1 * 32 + lane];
        float4 v2 = H[s2 * 32 + lane];
        float4 v3 = H[s3 * 32 + lane];
        a0.x += v0.x; a0.y += v0.y; a0.z += v0.z; a0.w += v0.w;
        a1.x += v1.x; a1.y += v1.y; a1.z += v1.z; a1.w += v1.w;
        a2.x += v2.x; a2.y += v2.y; a2.z += v2.z; a2.w += v2.w;
        a3.x += v3.x; a3.y += v3.y; a3.z += v3.z; a3.w += v3.w;
    }
    for (; e < end; e++) {
        int s = g_csr[e];
        float4 v = H[s * 32 + lane];
        a0.x += v.x; a0.y += v.y; a0.z += v.z; a0.w += v.w;
    }
    float4 bv = reinterpret_cast<const float4*>(b1)[lane];
    float4 o = make_float4(a0.x + a1.x + a2.x + a3.x + bv.x,
                           a0.y + a1.y + a2.y + a3.y + bv.y,
                           a0.z + a1.z + a2.z + a3.z + bv.z,
                           a0.w + a1.w + a2.w + a3.w + bv.w);
    reinterpret_cast<float4*>(g_out1)[gw * 32 + lane] = o;
}

// -------- layer-2 aggregate: HALF-warp per dst node, 16 x float4 = 64 ch --
__global__ __launch_bounds__(256) void agg64_kernel(const float* __restrict__ b2,
                                                    float* __restrict__ outp) {
    int ghw = (blockIdx.x * blockDim.x + threadIdx.x) >> 4;
    int lane = threadIdx.x & 15;
    if (ghw >= NODES) return;
    int beg = g_off[ghw], end = g_off[ghw + 1];
    const float4* __restrict__ H = reinterpret_cast<const float4*>(g_h2);

    float4 a0 = make_float4(0.f, 0.f, 0.f, 0.f);
    float4 a1 = make_float4(0.f, 0.f, 0.f, 0.f);
    float4 a2 = make_float4(0.f, 0.f, 0.f, 0.f);
    float4 a3 = make_float4(0.f, 0.f, 0.f, 0.f);
    int e = beg;
    for (; e + 3 < end; e += 4) {
        int s0 = g_csr[e];
        int s1 = g_csr[e + 1];
        int s2 = g_csr[e + 2];
        int s3 = g_csr[e + 3];
        float4 v0 = H[s0 * 16 + lane];
        float4 v1 = H[s1 * 16 + lane];
        float4 v2 = H[s2 * 16 + lane];
        float4 v3 = H[s3 * 16 + lane];
        a0.x += v0.x; a0.y += v0.y; a0.z += v0.z; a0.w += v0.w;
        a1.x += v1.x; a1.y += v1.y; a1.z += v1.z; a1.w += v1.w;
        a2.x += v2.x; a2.y += v2.y; a2.z += v2.z; a2.w += v2.w;
        a3.x += v3.x; a3.y += v3.y; a3.z += v3.z; a3.w += v3.w;
    }
    for (; e < end; e++) {
        int s = g_csr[e];
        float4 v = H[s * 16 + lane];
        a0.x += v.x; a0.y += v.y; a0.z += v.z; a0.w += v.w;
    }
    float4 bv = reinterpret_cast<const float4*>(b2)[lane];
    float4 o = make_float4(a0.x + a1.x + a2.x + a3.x + bv.x,
                           a0.y + a1.y + a2.y + a3.y + bv.y,
                           a0.z + a1.z + a2.z + a3.z + bv.z,
                           a0.w + a1.w + a2.w + a3.w + bv.w);
    reinterpret_cast<float4*>(outp)[ghw * 16 + lane] = o;
}

extern "C" void kernel_launch(void* const* d_in, const int* in_sizes, int n_in,
                              void* d_out, int out_size) {
    const float* x  = (const float*)d_in[0];
    const int*   ei = (const int*)d_in[1];   // [2, E]: src then dst
    const float* W1 = (const float*)d_in[2];
    const float* b1 = (const float*)d_in[3];
    const float* W2 = (const float*)d_in[4];
    const float* b2 = (const float*)d_in[5];
    float* outp = (float*)d_out;

    const int* src = ei;
    const int* dst = ei + EDGES;

    // resolve device-global addresses
    uint32_t *w1h, *w1l, *w2h, *w2l;
    void *odeg_p, *cnt_p;
    cudaGetSymbolAddress((void**)&w1h, g_w1h);
    cudaGetSymbolAddress((void**)&w1l, g_w1l);
    cudaGetSymbolAddress((void**)&w2h, g_w2h);
    cudaGetSymbolAddress((void**)&w2l, g_w2l);
    cudaGetSymbolAddress(&odeg_p, g_odeg);
    cudaGetSymbolAddress(&cnt_p, g_cnt);

    // ---- CSR build + weight split (single stream) ----
    cudaMemsetAsync(odeg_p, 0, NODES * sizeof(int));
    cudaMemsetAsync(cnt_p, 0, NODES * sizeof(int));
    wsplit_kernel<<<((IN_C / 2) * HID_C + 255) / 256, 256>>>(W1, W2);
    hist_kernel<<<(EDGES + 255) / 256, 256>>>(dst);      // in-degree only
    scan1_kernel<<<SCAN_NB, SCAN_B>>>();
    scan3_kernel<<<SCAN_NB, SCAN_B>>>();                 // per-block bsum reduce inside
    fill_kernel<<<(EDGES + 255) / 256, 256>>>(src, dst); // also builds out-degree

    // ---- layer 1: h1 = (x @ W1) * deg_inv ; out1 = b1 + sum_in h1 ----
    {
        dim3 grid(HID_C / 64, (NODES + 127) / 128);
        gemm_tc_kernel<HID_C, false><<<grid, 256>>>(x, w1h, w1l, NODES);
    }
    {
        long long threads = (long long)NODES * 32;
        agg128_kernel<<<(unsigned)((threads + 255) / 256), 256>>>(b1);
    }

    // ---- layer 2: h2 = (relu(out1) @ W2) * deg_inv ; out = b2 + sum_in h2 ----
    {
        dim3 grid(OUT_C / 64, (NODES + 127) / 128);
        gemm_tc_kernel<OUT_C, true><<<grid, 256>>>(nullptr, w2h, w2l, NODES);
    }
    {
        long long threads = (long long)NODES * 16;
        agg64_kernel<<<(unsigned)((threads + 255) / 256), 256>>>(b2, outp);
    }
}